// round 11
// baseline (speedup 1.0000x reference)
#include <cuda_runtime.h>
#include <cuda_bf16.h>

#define D      1024
#define BATCH  64
#define KV     4096
#define KV1    4097

// Scratch (no allocations allowed) ------------------------------------------
__device__ float g_cur[BATCH * D];
__device__ float g_q[BATCH * D];
__device__ float g_knew[BATCH * D];
__device__ float g_vnew[BATCH * D];
__device__ float g_attn[BATCH * D];
__device__ float g_sumexp[BATCH];

// ---------------------------------------------------------------------------
__global__ void init_kernel(const int* __restrict__ x, const float* __restrict__ emb,
                            const float* __restrict__ bq, const float* __restrict__ bk,
                            const float* __restrict__ bv, const float* __restrict__ bo,
                            float* __restrict__ out) {
    int b = blockIdx.x;
    int row = x[b];
    if (threadIdx.x == 0) g_sumexp[b] = 0.f;
    for (int i = threadIdx.x; i < D; i += blockDim.x) {
        g_cur[b * D + i]  = emb[(size_t)row * D + i];
        g_q[b * D + i]    = bq[i];
        g_knew[b * D + i] = bk[i];
        g_vnew[b * D + i] = bv[i];
        g_attn[b * D + i] = 0.f;
        out[b * D + i]    = bo[i];
    }
}

// ---------------------------------------------------------------------------
// Split-K GEMM: C[b,e] += sum_{k in 64-slice} A[b,k] * W[e,k]
// mode 0: A=g_cur, z selects (Wq->g_q, Wk->g_knew, Wv->g_vnew), grid (16,16,3)
// mode 1: A=g_attn (scaled by 1/sumexp[b] at the accumulator), C=Cext
__global__ void gemm_splitk(int mode, const float* __restrict__ Wa,
                            const float* __restrict__ Wb, const float* __restrict__ Wc,
                            float* __restrict__ Cext) {
    const float* A = (mode == 0) ? g_cur : g_attn;
    const float* W = (mode == 0)
        ? (blockIdx.z == 0 ? Wa : blockIdx.z == 1 ? Wb : Wc) : Wa;
    float* C = (mode == 0)
        ? (blockIdx.z == 0 ? g_q : blockIdx.z == 1 ? g_knew : g_vnew) : Cext;

    __shared__ float As[64][65];
    __shared__ float Ws[64][65];
    const int e0 = blockIdx.x * 64;
    const int k0 = blockIdx.y * 64;              // single 64-wide K slice
    const int tid = threadIdx.x;
    const int ty = tid >> 4, tx = tid & 15;
    float acc[4][4] = {};

    for (int i = tid; i < 1024; i += 256) {
        int row = i >> 4;
        int c4  = (i & 15) * 4;
        float4 a = *(const float4*)(A + (size_t)row * D + k0 + c4);
        As[row][c4 + 0] = a.x; As[row][c4 + 1] = a.y;
        As[row][c4 + 2] = a.z; As[row][c4 + 3] = a.w;
        float4 w = *(const float4*)(W + (size_t)(e0 + row) * D + k0 + c4);
        Ws[row][c4 + 0] = w.x; Ws[row][c4 + 1] = w.y;
        Ws[row][c4 + 2] = w.z; Ws[row][c4 + 3] = w.w;
    }
    __syncthreads();
    #pragma unroll
    for (int kk = 0; kk < 64; kk++) {
        float av[4], wv[4];
        #pragma unroll
        for (int i = 0; i < 4; i++) av[i] = As[ty * 4 + i][kk];
        #pragma unroll
        for (int j = 0; j < 4; j++) wv[j] = Ws[tx * 4 + j][kk];
        #pragma unroll
        for (int i = 0; i < 4; i++)
            #pragma unroll
            for (int j = 0; j < 4; j++) acc[i][j] += av[i] * wv[j];
    }
    #pragma unroll
    for (int i = 0; i < 4; i++) {
        int b = ty * 4 + i;
        float scale = (mode == 1) ? (1.0f / g_sumexp[b]) : 1.0f;
        #pragma unroll
        for (int j = 0; j < 4; j++) {
            int e = e0 + tx * 4 + j;
            atomicAdd(&C[(size_t)b * D + e], acc[i][j] * scale);
        }
    }
}

// ---------------------------------------------------------------------------
// Fully fused attention stream. Block = (b, 128-row s-chunk), 512 threads.
// Phase 1: per-warp rows — dot(q,k), copy k rows, w = exp(score) into smem.
// Phase 2: per-thread columns — copy v rows, accumulate unnormalized w*v.
// Normalization deferred to the output GEMM via g_sumexp.
__global__ void stream_fused_kernel(const float* __restrict__ prev_k,
                                    const float* __restrict__ prev_v,
                                    float* __restrict__ k_out,
                                    float* __restrict__ v_out) {
    const int b = blockIdx.x;
    const int s0 = blockIdx.y * 128;
    const bool last = (blockIdx.y == 31);
    const int tid = threadIdx.x;
    const int wid = tid >> 5, lane = tid & 31;

    __shared__ float4 qs[D / 4];
    __shared__ float ps[129];
    for (int i = tid; i < D / 4; i += 512)
        qs[i] = ((const float4*)(g_q + b * D))[i];
    __syncthreads();

    // ---- Phase 1: k rows (8 consecutive rows per warp) ----
    #pragma unroll 1
    for (int r = 0; r < 8; r++) {
        int sl = wid * 8 + r;
        int s = s0 + sl;
        const float4* src = (const float4*)(prev_k + ((size_t)b * KV + s) * D);
        float4* dst = (float4*)(k_out + ((size_t)b * KV1 + s) * D);
        float4 kv[8];
        #pragma unroll
        for (int i = 0; i < 8; i++) kv[i] = __ldcs(src + lane + i * 32);
        float acc = 0.f;
        #pragma unroll
        for (int i = 0; i < 8; i++) {
            float4 qv = qs[lane + i * 32];
            acc += kv[i].x * qv.x + kv[i].y * qv.y + kv[i].z * qv.z + kv[i].w * qv.w;
            __stcs(dst + lane + i * 32, kv[i]);
        }
        #pragma unroll
        for (int o = 16; o; o >>= 1) acc += __shfl_xor_sync(0xffffffffu, acc, o);
        if (lane == 0) ps[sl] = __expf(acc * 0.03125f);
    }
    if (last && wid == 15) {                      // new row s = 4096 (k side)
        const float4* src = (const float4*)(g_knew + b * D);
        float4* dst = (float4*)(k_out + ((size_t)b * KV1 + KV) * D);
        float4 kv[8];
        #pragma unroll
        for (int i = 0; i < 8; i++) kv[i] = src[lane + i * 32];
        float acc = 0.f;
        #pragma unroll
        for (int i = 0; i < 8; i++) {
            float4 qv = qs[lane + i * 32];
            acc += kv[i].x * qv.x + kv[i].y * qv.y + kv[i].z * qv.z + kv[i].w * qv.w;
            __stcs(dst + lane + i * 32, kv[i]);
        }
        #pragma unroll
        for (int o = 16; o; o >>= 1) acc += __shfl_xor_sync(0xffffffffu, acc, o);
        if (lane == 0) ps[128] = __expf(acc * 0.03125f);
    }
    __syncthreads();

    // ---- sumexp contribution (warp 0) ----
    if (wid == 0) {
        float s = ps[lane] + ps[lane + 32] + ps[lane + 64] + ps[lane + 96];
        if (last && lane == 0) s += ps[128];
        #pragma unroll
        for (int o = 16; o; o >>= 1) s += __shfl_xor_sync(0xffffffffu, s, o);
        if (lane == 0) atomicAdd(&g_sumexp[b], s);
    }

    // ---- Phase 2: v rows (2 threads per float4-column, 64 rows each) ----
    const int col = tid & 255;
    const int sbeg = (tid >> 8) * 64;
    const float4* vbase = (const float4*)(prev_v + (size_t)b * KV * D) + col;
    float4* obase = (float4*)(v_out + (size_t)b * KV1 * D) + col;

    float4 acc4 = make_float4(0.f, 0.f, 0.f, 0.f);
    for (int s = 0; s < 64; s += 8) {
        float4 val[8];
        #pragma unroll
        for (int j = 0; j < 8; j++)
            val[j] = __ldcs(vbase + (size_t)(s0 + sbeg + s + j) * (D / 4));
        #pragma unroll
        for (int j = 0; j < 8; j++) {
            float w = ps[sbeg + s + j];
            acc4.x += w * val[j].x; acc4.y += w * val[j].y;
            acc4.z += w * val[j].z; acc4.w += w * val[j].w;
            __stcs(obase + (size_t)(s0 + sbeg + s + j) * (D / 4), val[j]);
        }
    }
    if (last && sbeg == 0) {                      // new row s = 4096 (v side)
        float4 val = ((const float4*)(g_vnew + b * D))[col];
        float w = ps[128];
        acc4.x += w * val.x; acc4.y += w * val.y;
        acc4.z += w * val.z; acc4.w += w * val.w;
        __stcs(obase + (size_t)KV * (D / 4), val);
    }
    float* ga = g_attn + b * D + col * 4;
    atomicAdd(ga + 0, acc4.x);
    atomicAdd(ga + 1, acc4.y);
    atomicAdd(ga + 2, acc4.z);
    atomicAdd(ga + 3, acc4.w);
}

// ---------------------------------------------------------------------------
extern "C" void kernel_launch(void* const* d_in, const int* in_sizes, int n_in,
                              void* d_out, int out_size) {
    const int*   x      = (const int*)d_in[0];
    const float* prev_k = (const float*)d_in[1];
    const float* prev_v = (const float*)d_in[2];
    const float* emb    = (const float*)d_in[3];
    const float* Wq     = (const float*)d_in[4];
    const float* bq     = (const float*)d_in[5];
    const float* Wk     = (const float*)d_in[6];
    const float* bk     = (const float*)d_in[7];
    const float* Wv     = (const float*)d_in[8];
    const float* bv     = (const float*)d_in[9];
    const float* Wo     = (const float*)d_in[10];
    const float* bo     = (const float*)d_in[11];

    float* out   = (float*)d_out;                       // (64, 1, 1024)
    float* k_out = out + (size_t)BATCH * D;             // (64, 4097, 1024)
    float* v_out = k_out + (size_t)BATCH * KV1 * D;     // (64, 4097, 1024)

    init_kernel<<<BATCH, 256>>>(x, emb, bq, bk, bv, bo, out);
    gemm_splitk<<<dim3(16, 16, 3), 256>>>(0, Wq, Wk, Wv, nullptr);
    stream_fused_kernel<<<dim3(BATCH, 32), 512>>>(prev_k, prev_v, k_out, v_out);
    gemm_splitk<<<dim3(16, 16, 1), 256>>>(1, Wo, nullptr, nullptr, out);
}

// round 12
// speedup vs baseline: 1.0040x; 1.0040x over previous
#include <cuda_runtime.h>
#include <cuda_bf16.h>

#define D      1024
#define BATCH  64
#define KV     4096
#define KV1    4097
#define NCHUNK 32

// Scratch (no allocations allowed) ------------------------------------------
__device__ float g_cur[BATCH * D];
__device__ float g_q[BATCH * D];
__device__ float g_knew[BATCH * D];
__device__ float g_vnew[BATCH * D];
__device__ float g_scores[BATCH * KV1];   // holds exp(score) (unnormalized)
__device__ float g_attn[BATCH * D];
__device__ float g_sumexp[BATCH];

// ---------------------------------------------------------------------------
__global__ void init_kernel(const int* __restrict__ x, const float* __restrict__ emb,
                            const float* __restrict__ bq, const float* __restrict__ bk,
                            const float* __restrict__ bv, const float* __restrict__ bo,
                            float* __restrict__ out) {
    int b = blockIdx.x;
    int row = x[b];
    if (threadIdx.x == 0) g_sumexp[b] = 0.f;
    for (int i = threadIdx.x; i < D; i += blockDim.x) {
        g_cur[b * D + i]  = emb[(size_t)row * D + i];
        g_q[b * D + i]    = bq[i];
        g_knew[b * D + i] = bk[i];
        g_vnew[b * D + i] = bv[i];
        g_attn[b * D + i] = 0.f;
        out[b * D + i]    = bo[i];
    }
}

// ---------------------------------------------------------------------------
// Split-K GEMM, 32-wide e-tile: C[b,e] += sum_{k in 64-slice} A[b,k] * W[e,k]
// mode 0: A=g_cur, z selects (Wq->g_q, Wk->g_knew, Wv->g_vnew), grid (32,16,3)
// mode 1: A=g_attn scaled by 1/g_sumexp[b] at accumulation, C=Cext, grid (32,16)
__global__ void gemm_splitk(int mode, const float* __restrict__ Wa,
                            const float* __restrict__ Wb, const float* __restrict__ Wc,
                            float* __restrict__ Cext) {
    const float* A = (mode == 0) ? g_cur : g_attn;
    const float* W = (mode == 0)
        ? (blockIdx.z == 0 ? Wa : blockIdx.z == 1 ? Wb : Wc) : Wa;
    float* C = (mode == 0)
        ? (blockIdx.z == 0 ? g_q : blockIdx.z == 1 ? g_knew : g_vnew) : Cext;

    __shared__ float As[64][65];      // 64 b-rows x 64 k
    __shared__ float Ws[32][65];      // 32 e-rows x 64 k
    const int e0 = blockIdx.x * 32;
    const int k0 = blockIdx.y * 64;
    const int tid = threadIdx.x;
    const int ty = tid >> 4, tx = tid & 15;
    float acc[4][2] = {};

    for (int i = tid; i < 1024; i += 256) {       // A: 1024 float4
        int row = i >> 4;
        int c4  = (i & 15) * 4;
        float4 a = *(const float4*)(A + (size_t)row * D + k0 + c4);
        As[row][c4 + 0] = a.x; As[row][c4 + 1] = a.y;
        As[row][c4 + 2] = a.z; As[row][c4 + 3] = a.w;
    }
    for (int i = tid; i < 512; i += 256) {        // W: 512 float4
        int row = i >> 4;
        int c4  = (i & 15) * 4;
        float4 w = *(const float4*)(W + (size_t)(e0 + row) * D + k0 + c4);
        Ws[row][c4 + 0] = w.x; Ws[row][c4 + 1] = w.y;
        Ws[row][c4 + 2] = w.z; Ws[row][c4 + 3] = w.w;
    }
    __syncthreads();
    #pragma unroll
    for (int kk = 0; kk < 64; kk++) {
        float av[4], wv[2];
        #pragma unroll
        for (int i = 0; i < 4; i++) av[i] = As[ty * 4 + i][kk];
        #pragma unroll
        for (int j = 0; j < 2; j++) wv[j] = Ws[tx * 2 + j][kk];
        #pragma unroll
        for (int i = 0; i < 4; i++)
            #pragma unroll
            for (int j = 0; j < 2; j++) acc[i][j] += av[i] * wv[j];
    }
    #pragma unroll
    for (int i = 0; i < 4; i++) {
        int b = ty * 4 + i;
        float scale = (mode == 1) ? (1.0f / g_sumexp[b]) : 1.0f;
        #pragma unroll
        for (int j = 0; j < 2; j++) {
            int e = e0 + tx * 2 + j;
            atomicAdd(&C[(size_t)b * D + e], acc[i][j] * scale);
        }
    }
}

// ---------------------------------------------------------------------------
// Fused: g_scores[b,s] = exp(q.k/32)  AND  k_out[b,s,:] = k[b,s,:]
// One warp per s-row; 16 rows per 512-thread block; MLP=8 front-batched loads.
// Per-block single atomicAdd of the local sum of exps into g_sumexp[b].
__global__ void scores_copy_kernel(const float* __restrict__ prev_k,
                                   float* __restrict__ k_out) {
    int b = blockIdx.x;
    __shared__ float4 qs[D / 4];
    __shared__ float esum[16];
    for (int i = threadIdx.x; i < D / 4; i += blockDim.x)
        qs[i] = ((const float4*)(g_q + b * D))[i];
    __syncthreads();

    int wid = threadIdx.x >> 5, lane = threadIdx.x & 31;
    int s = blockIdx.y * 16 + wid;

    float e = 0.f;
    if (s <= KV) {
        const float4* src = (s < KV)
            ? (const float4*)(prev_k + ((size_t)b * KV + s) * D)
            : (const float4*)(g_knew + b * D);
        float4* dst = (float4*)(k_out + ((size_t)b * KV1 + s) * D);

        float4 kv[8];
        #pragma unroll
        for (int i = 0; i < 8; i++) kv[i] = __ldcs(src + lane + i * 32);

        float acc = 0.f;
        #pragma unroll
        for (int i = 0; i < 8; i++) {
            float4 qv = qs[lane + i * 32];
            acc += kv[i].x * qv.x + kv[i].y * qv.y + kv[i].z * qv.z + kv[i].w * qv.w;
            __stcs(dst + lane + i * 32, kv[i]);
        }
        #pragma unroll
        for (int o = 16; o; o >>= 1) acc += __shfl_xor_sync(0xffffffffu, acc, o);
        e = __expf(acc * 0.03125f);               // 1/sqrt(1024)
        if (lane == 0) g_scores[b * KV1 + s] = e;
    }
    if (lane == 0) esum[wid] = e;
    __syncthreads();
    if (wid == 0) {
        float v = (lane < 16) ? esum[lane] : 0.f;
        #pragma unroll
        for (int o = 16; o; o >>= 1) v += __shfl_xor_sync(0xffffffffu, v, o);
        if (lane == 0) atomicAdd(&g_sumexp[b], v);
    }
}

// ---------------------------------------------------------------------------
// Fused: g_attn[b,d] += sum_{s in chunk} w[s]*v[b,s,d]  AND copy v rows.
// w = g_scores (already exp, unnormalized). Block = (b, 128-row s-chunk).
__global__ void attn_copy_kernel(const float* __restrict__ prev_v,
                                 float* __restrict__ v_out) {
    int b = blockIdx.x;
    int s0 = blockIdx.y * 128;
    int t = threadIdx.x;
    const float* p = g_scores + b * KV1;
    __shared__ float ps[128];
    if (t < 128) ps[t] = p[s0 + t];
    __syncthreads();

    const float4* vbase = (const float4*)(prev_v + (size_t)b * KV * D) + t;
    float4* obase = (float4*)(v_out + (size_t)b * KV1 * D) + t;

    float4 acc = make_float4(0.f, 0.f, 0.f, 0.f);
    for (int s = 0; s < 128; s += 8) {
        float4 val[8];
        #pragma unroll
        for (int j = 0; j < 8; j++)
            val[j] = __ldcs(vbase + (size_t)(s0 + s + j) * (D / 4));
        #pragma unroll
        for (int j = 0; j < 8; j++) {
            float w = ps[s + j];
            acc.x += w * val[j].x; acc.y += w * val[j].y;
            acc.z += w * val[j].z; acc.w += w * val[j].w;
            __stcs(obase + (size_t)(s0 + s + j) * (D / 4), val[j]);
        }
    }
    if (blockIdx.y == NCHUNK - 1) {               // new row s = 4096
        float4 val = ((const float4*)(g_vnew + b * D))[t];
        float w = p[KV];
        acc.x += w * val.x; acc.y += w * val.y;
        acc.z += w * val.z; acc.w += w * val.w;
        __stcs(obase + (size_t)KV * (D / 4), val);
    }
    float* ga = g_attn + b * D + t * 4;
    atomicAdd(ga + 0, acc.x);
    atomicAdd(ga + 1, acc.y);
    atomicAdd(ga + 2, acc.z);
    atomicAdd(ga + 3, acc.w);
}

// ---------------------------------------------------------------------------
extern "C" void kernel_launch(void* const* d_in, const int* in_sizes, int n_in,
                              void* d_out, int out_size) {
    const int*   x      = (const int*)d_in[0];
    const float* prev_k = (const float*)d_in[1];
    const float* prev_v = (const float*)d_in[2];
    const float* emb    = (const float*)d_in[3];
    const float* Wq     = (const float*)d_in[4];
    const float* bq     = (const float*)d_in[5];
    const float* Wk     = (const float*)d_in[6];
    const float* bk     = (const float*)d_in[7];
    const float* Wv     = (const float*)d_in[8];
    const float* bv     = (const float*)d_in[9];
    const float* Wo     = (const float*)d_in[10];
    const float* bo     = (const float*)d_in[11];

    float* out   = (float*)d_out;                       // (64, 1, 1024)
    float* k_out = out + (size_t)BATCH * D;             // (64, 4097, 1024)
    float* v_out = k_out + (size_t)BATCH * KV1 * D;     // (64, 4097, 1024)

    init_kernel<<<BATCH, 256>>>(x, emb, bq, bk, bv, bo, out);
    gemm_splitk<<<dim3(32, 16, 3), 256>>>(0, Wq, Wk, Wv, nullptr);
    scores_copy_kernel<<<dim3(BATCH, 257), 512>>>(prev_k, k_out);
    attn_copy_kernel<<<dim3(BATCH, NCHUNK), 256>>>(prev_v, v_out);
    gemm_splitk<<<dim3(32, 16, 1), 256>>>(1, Wo, nullptr, nullptr, out);
}

// round 13
// speedup vs baseline: 1.0190x; 1.0149x over previous
#include <cuda_runtime.h>
#include <cuda_bf16.h>

#define D      1024
#define BATCH  64
#define KV     4096
#define KV1    4097
#define NCHUNK 32

// Scratch (no allocations allowed) ------------------------------------------
__device__ float g_cur[BATCH * D];
__device__ float g_q[BATCH * D];
__device__ float g_knew[BATCH * D];
__device__ float g_vnew[BATCH * D];
__device__ float g_scores[BATCH * KV1];   // holds exp(score) (unnormalized)
__device__ float g_attn[BATCH * D];
__device__ float g_sumexp[BATCH];
__device__ int   g_ready[BATCH * NCHUNK]; // scores->attn chunk readiness flags

// ---------------------------------------------------------------------------
__global__ void init_kernel(const int* __restrict__ x, const float* __restrict__ emb,
                            const float* __restrict__ bq, const float* __restrict__ bk,
                            const float* __restrict__ bv, const float* __restrict__ bo,
                            float* __restrict__ out) {
    int b = blockIdx.x;
    int row = x[b];
    if (threadIdx.x == 0) g_sumexp[b] = 0.f;
    if (threadIdx.x < NCHUNK) g_ready[b * NCHUNK + threadIdx.x] = 0;
    for (int i = threadIdx.x; i < D; i += blockDim.x) {
        g_cur[b * D + i]  = emb[(size_t)row * D + i];
        g_q[b * D + i]    = bq[i];
        g_knew[b * D + i] = bk[i];
        g_vnew[b * D + i] = bv[i];
        g_attn[b * D + i] = 0.f;
        out[b * D + i]    = bo[i];
    }
}

// ---------------------------------------------------------------------------
// Split-K GEMM, 32-wide e-tile: C[b,e] += sum_{k in 64-slice} A[b,k] * W[e,k]
// mode 0: A=g_cur, z selects (Wq->g_q, Wk->g_knew, Wv->g_vnew), grid (32,16,3)
// mode 1: A=g_attn scaled by 1/g_sumexp[b] at accumulation, C=Cext, grid (32,16)
__global__ void gemm_splitk(int mode, const float* __restrict__ Wa,
                            const float* __restrict__ Wb, const float* __restrict__ Wc,
                            float* __restrict__ Cext) {
    const float* A = (mode == 0) ? g_cur : g_attn;
    const float* W = (mode == 0)
        ? (blockIdx.z == 0 ? Wa : blockIdx.z == 1 ? Wb : Wc) : Wa;
    float* C = (mode == 0)
        ? (blockIdx.z == 0 ? g_q : blockIdx.z == 1 ? g_knew : g_vnew) : Cext;

    __shared__ float As[64][65];
    __shared__ float Ws[32][65];
    const int e0 = blockIdx.x * 32;
    const int k0 = blockIdx.y * 64;
    const int tid = threadIdx.x;
    const int ty = tid >> 4, tx = tid & 15;
    float acc[4][2] = {};

    for (int i = tid; i < 1024; i += 256) {
        int row = i >> 4;
        int c4  = (i & 15) * 4;
        float4 a = *(const float4*)(A + (size_t)row * D + k0 + c4);
        As[row][c4 + 0] = a.x; As[row][c4 + 1] = a.y;
        As[row][c4 + 2] = a.z; As[row][c4 + 3] = a.w;
    }
    for (int i = tid; i < 512; i += 256) {
        int row = i >> 4;
        int c4  = (i & 15) * 4;
        float4 w = *(const float4*)(W + (size_t)(e0 + row) * D + k0 + c4);
        Ws[row][c4 + 0] = w.x; Ws[row][c4 + 1] = w.y;
        Ws[row][c4 + 2] = w.z; Ws[row][c4 + 3] = w.w;
    }
    __syncthreads();
    #pragma unroll
    for (int kk = 0; kk < 64; kk++) {
        float av[4], wv[2];
        #pragma unroll
        for (int i = 0; i < 4; i++) av[i] = As[ty * 4 + i][kk];
        #pragma unroll
        for (int j = 0; j < 2; j++) wv[j] = Ws[tx * 2 + j][kk];
        #pragma unroll
        for (int i = 0; i < 4; i++)
            #pragma unroll
            for (int j = 0; j < 2; j++) acc[i][j] += av[i] * wv[j];
    }
    #pragma unroll
    for (int i = 0; i < 4; i++) {
        int b = ty * 4 + i;
        float scale = (mode == 1) ? (1.0f / g_sumexp[b]) : 1.0f;
        #pragma unroll
        for (int j = 0; j < 2; j++) {
            int e = e0 + tx * 2 + j;
            atomicAdd(&C[(size_t)b * D + e], acc[i][j] * scale);
        }
    }
}

// ---------------------------------------------------------------------------
// Single stream launch. grid (BATCH, 289), 512 threads.
//  y in [0,257): scores role — 16 k-rows, writes exp(score)+k_out, flags chunk.
//  y in [257,289): attn role — waits for its chunk's flags, streams 128 v rows.
__global__ void stream_kernel(const float* __restrict__ prev_k,
                              const float* __restrict__ prev_v,
                              float* __restrict__ k_out,
                              float* __restrict__ v_out) {
    const int b = blockIdx.x;
    const int y = blockIdx.y;
    const int tid = threadIdx.x;
    const int wid = tid >> 5, lane = tid & 31;

    __shared__ float4 qs[D / 4];
    __shared__ float ps[132];          // scores: esum[16] reuse; attn: 129 weights

    if (y < 257) {
        // ================= scores role =================
        for (int i = tid; i < D / 4; i += 512)
            qs[i] = ((const float4*)(g_q + b * D))[i];
        __syncthreads();

        int s = y * 16 + wid;
        float e = 0.f;
        if (s <= KV) {
            const float4* src = (s < KV)
                ? (const float4*)(prev_k + ((size_t)b * KV + s) * D)
                : (const float4*)(g_knew + b * D);
            float4* dst = (float4*)(k_out + ((size_t)b * KV1 + s) * D);

            float4 kv[8];
            #pragma unroll
            for (int i = 0; i < 8; i++) kv[i] = __ldcs(src + lane + i * 32);

            float acc = 0.f;
            #pragma unroll
            for (int i = 0; i < 8; i++) {
                float4 qv = qs[lane + i * 32];
                acc += kv[i].x * qv.x + kv[i].y * qv.y + kv[i].z * qv.z + kv[i].w * qv.w;
                __stcs(dst + lane + i * 32, kv[i]);
            }
            #pragma unroll
            for (int o = 16; o; o >>= 1) acc += __shfl_xor_sync(0xffffffffu, acc, o);
            e = __expf(acc * 0.03125f);            // 1/sqrt(1024)
            if (lane == 0) g_scores[b * KV1 + s] = e;
        }
        if (lane == 0) ps[wid] = e;
        __syncthreads();
        if (tid < 32) {
            float v = (tid < 16) ? ps[tid] : 0.f;
            #pragma unroll
            for (int o = 16; o; o >>= 1) v += __shfl_xor_sync(0xffffffffu, v, o);
            if (tid == 0) {
                atomicAdd(&g_sumexp[b], v);
                __threadfence();
                int chunk = y >> 3; if (chunk > 31) chunk = 31;
                atomicAdd(&g_ready[b * NCHUNK + chunk], 1);
            }
        }
    } else {
        // ================= attn role =================
        const int chunk = y - 257;
        const int s0 = chunk * 128;
        const bool last = (chunk == NCHUNK - 1);
        const int target = last ? 9 : 8;

        if (tid == 0) {
            while (atomicAdd(&g_ready[b * NCHUNK + chunk], 0) < target) { }
        }
        __syncthreads();
        __threadfence();

        const float* p = g_scores + b * KV1;
        if (tid < 128) ps[tid] = p[s0 + tid];
        if (last && tid == 128) ps[128] = p[KV];
        __syncthreads();

        const int col = tid & 255;
        const int rbeg = (tid >> 8) * 64;
        const float4* vbase = (const float4*)(prev_v + (size_t)b * KV * D) + col;
        float4* obase = (float4*)(v_out + (size_t)b * KV1 * D) + col;

        float4 acc = make_float4(0.f, 0.f, 0.f, 0.f);
        for (int s = 0; s < 64; s += 8) {
            float4 val[8];
            #pragma unroll
            for (int j = 0; j < 8; j++)
                val[j] = __ldcs(vbase + (size_t)(s0 + rbeg + s + j) * (D / 4));
            #pragma unroll
            for (int j = 0; j < 8; j++) {
                float w = ps[rbeg + s + j];
                acc.x += w * val[j].x; acc.y += w * val[j].y;
                acc.z += w * val[j].z; acc.w += w * val[j].w;
                __stcs(obase + (size_t)(s0 + rbeg + s + j) * (D / 4), val[j]);
            }
        }
        if (last && rbeg == 0) {                   // new row s = 4096
            float4 val = ((const float4*)(g_vnew + b * D))[col];
            float w = ps[128];
            acc.x += w * val.x; acc.y += w * val.y;
            acc.z += w * val.z; acc.w += w * val.w;
            __stcs(obase + (size_t)KV * (D / 4), val);
        }
        float* ga = g_attn + b * D + col * 4;
        atomicAdd(ga + 0, acc.x);
        atomicAdd(ga + 1, acc.y);
        atomicAdd(ga + 2, acc.z);
        atomicAdd(ga + 3, acc.w);
    }
}

// ---------------------------------------------------------------------------
extern "C" void kernel_launch(void* const* d_in, const int* in_sizes, int n_in,
                              void* d_out, int out_size) {
    const int*   x      = (const int*)d_in[0];
    const float* prev_k = (const float*)d_in[1];
    const float* prev_v = (const float*)d_in[2];
    const float* emb    = (const float*)d_in[3];
    const float* Wq     = (const float*)d_in[4];
    const float* bq     = (const float*)d_in[5];
    const float* Wk     = (const float*)d_in[6];
    const float* bk     = (const float*)d_in[7];
    const float* Wv     = (const float*)d_in[8];
    const float* bv     = (const float*)d_in[9];
    const float* Wo     = (const float*)d_in[10];
    const float* bo     = (const float*)d_in[11];

    float* out   = (float*)d_out;                       // (64, 1, 1024)
    float* k_out = out + (size_t)BATCH * D;             // (64, 4097, 1024)
    float* v_out = k_out + (size_t)BATCH * KV1 * D;     // (64, 4097, 1024)

    init_kernel<<<BATCH, 256>>>(x, emb, bq, bk, bv, bo, out);
    gemm_splitk<<<dim3(32, 16, 3), 256>>>(0, Wq, Wk, Wv, nullptr);
    stream_kernel<<<dim3(BATCH, 289), 512>>>(prev_k, prev_v, k_out, v_out);
    gemm_splitk<<<dim3(32, 16, 1), 256>>>(1, Wo, nullptr, nullptr, out);
}